// round 1
// baseline (speedup 1.0000x reference)
#include <cuda_runtime.h>

typedef unsigned long long u64;

#define HIDN 10
#define CCH  256
#define HWV  16384
#define NIMG 8
// output offsets (floats)
#define OUT_XHL  1310720
#define OUT_ATTU 2621440
#define OUT_ATTL 2752512

// ---------- packed f32x2 helpers ----------
__device__ __forceinline__ u64 ffma2(u64 a, u64 b, u64 c) {
    u64 d; asm("fma.rn.f32x2 %0,%1,%2,%3;" : "=l"(d) : "l"(a), "l"(b), "l"(c)); return d;
}
__device__ __forceinline__ u64 fmul2(u64 a, u64 b) {
    u64 d; asm("mul.rn.f32x2 %0,%1,%2;" : "=l"(d) : "l"(a), "l"(b)); return d;
}
__device__ __forceinline__ u64 fadd2(u64 a, u64 b) {
    u64 d; asm("add.rn.f32x2 %0,%1,%2;" : "=l"(d) : "l"(a), "l"(b)); return d;
}
__device__ __forceinline__ u64 pack2(float x, float y) {
    u64 d; asm("mov.b64 %0,{%1,%2};" : "=l"(d) : "f"(x), "f"(y)); return d;
}
__device__ __forceinline__ void unpack2(u64 a, float& x, float& y) {
    asm("mov.b64 {%0,%1},%2;" : "=f"(x), "=f"(y) : "l"(a));
}
__device__ __forceinline__ u64 dup2(float x) { return pack2(x, x); }
__device__ __forceinline__ u64 relu2(u64 a) {
    float x, y; unpack2(a, x, y);
    return pack2(fmaxf(x, 0.f), fmaxf(y, 0.f));
}
__device__ __forceinline__ u64 sigmoid2(u64 a) {
    float x, y; unpack2(a, x, y);
    x = __fdividef(1.f, 1.f + __expf(-x));
    y = __fdividef(1.f, 1.f + __expf(-y));
    return pack2(x, y);
}
__device__ __forceinline__ u64 neg2(u64 a) { return a ^ 0x8000000080000000ULL; }

struct P27 {
    const float* a[27];
    float* out;
};

// small-weight smem offsets (u64 units), all values duplicated (w,w)
// 0    : pdp_w1 tail [o*20+k] (400)       o<20, k: 0..9 xh_u, 10..19 xh_l
// 400  : pdp_w2 flat (200)                [g*100+o*10+i]
// 600  : att_w (20), 620: att_b (2)
// 622  : compU_att_w (40), 662: compU_att_b (4), 666: compU_w (200)
// 866  : compL_att_w (20), 886: compL_att_b (2), 888: compL_w (200)
// 1088 : decU_att tail (20), 1108: decU_att_b (1), 1109: decU_w (100)
// 1209 : decL_att tail (20), 1229: decL_att_b (1), 1230: decL_w (100)
// 1330 : updU_gate_w (200), 1530: updU_gate_b (10), 1540: updU_cand_w (200)
// 1740 : updL_gate_w (200), 1940: updL_gate_b (10), 1950: updL_cand_w (200)

__global__ void __launch_bounds__(256) hg_kernel(P27 p) {
    const float* g_hfea = p.a[0];
    const float* g_xhu  = p.a[1];
    const float* g_xhl  = p.a[2];
    const float* g_xf   = p.a[3];
    const float* g_xp   = p.a[4];
    const float* w_pdp1 = p.a[5];
    const float* w_pdp2 = p.a[6];
    const float* w_att  = p.a[7];
    const float* b_att  = p.a[8];
    const float* w_cua  = p.a[9];
    const float* b_cua  = p.a[10];
    const float* w_cu   = p.a[11];
    const float* w_cla  = p.a[12];
    const float* b_cla  = p.a[13];
    const float* w_cl   = p.a[14];
    const float* w_dua  = p.a[15];
    const float* b_dua  = p.a[16];
    const float* w_du   = p.a[17];
    const float* w_dla  = p.a[18];
    const float* b_dla  = p.a[19];
    const float* w_dl   = p.a[20];
    const float* w_ugu  = p.a[21];
    const float* b_ugu  = p.a[22];
    const float* w_ucu  = p.a[23];
    const float* w_ugl  = p.a[24];
    const float* b_ugl  = p.a[25];
    const float* w_ucl  = p.a[26];
    float* out = p.out;

    __shared__ u64 s_big[256 * 12];   // per-channel 24 floats: 20 pdp rows + decU + decL + 2 pad
    __shared__ u64 s_small[2150];

    const int tid = threadIdx.x;
    {
        float* bigf = (float*)s_big;
        for (int i = tid; i < 256 * 24; i += 256) {
            int c = i / 24, j = i % 24;
            float w = 0.f;
            if (j < 20)       w = w_pdp1[j * 276 + c];
            else if (j == 20) w = w_dua[c];
            else if (j == 21) w = w_dla[c];
            bigf[i] = w;
        }
        for (int i = tid; i < 400; i += 256) { int o = i / 20, k = i % 20; s_small[i] = dup2(w_pdp1[o * 276 + 256 + k]); }
        for (int i = tid; i < 200; i += 256) s_small[400 + i] = dup2(w_pdp2[i]);
        for (int i = tid; i < 22;  i += 256) s_small[600 + i] = (i < 20) ? dup2(w_att[i]) : dup2(b_att[i - 20]);
        for (int i = tid; i < 44;  i += 256) s_small[622 + i] = (i < 40) ? dup2(w_cua[i]) : dup2(b_cua[i - 40]);
        for (int i = tid; i < 200; i += 256) s_small[666 + i] = dup2(w_cu[i]);
        for (int i = tid; i < 22;  i += 256) s_small[866 + i] = (i < 20) ? dup2(w_cla[i]) : dup2(b_cla[i - 20]);
        for (int i = tid; i < 200; i += 256) s_small[888 + i] = dup2(w_cl[i]);
        for (int i = tid; i < 21;  i += 256) s_small[1088 + i] = (i < 20) ? dup2(w_dua[256 + i]) : dup2(b_dua[0]);
        for (int i = tid; i < 100; i += 256) s_small[1109 + i] = dup2(w_du[i]);
        for (int i = tid; i < 21;  i += 256) s_small[1209 + i] = (i < 20) ? dup2(w_dla[256 + i]) : dup2(b_dla[0]);
        for (int i = tid; i < 100; i += 256) s_small[1230 + i] = dup2(w_dl[i]);
        for (int i = tid; i < 210; i += 256) s_small[1330 + i] = (i < 200) ? dup2(w_ugu[i]) : dup2(b_ugu[i - 200]);
        for (int i = tid; i < 200; i += 256) s_small[1540 + i] = dup2(w_ucu[i]);
        for (int i = tid; i < 210; i += 256) s_small[1740 + i] = (i < 200) ? dup2(w_ugl[i]) : dup2(b_ugl[i - 200]);
        for (int i = tid; i < 200; i += 256) s_small[1950 + i] = dup2(w_ucl[i]);
    }
    __syncthreads();

    // warp-strided work assignment: 2048 working warps, 32 pixel-pairs each.
    const int wib  = tid >> 5;
    const int lane = tid & 31;
    const int gw   = (int)blockIdx.x + 296 * wib;
    if (gw >= 2048) return;
    const int pair = gw * 32 + lane;
    const int pix  = pair * 2;
    const int n    = pix >> 14;
    const int hw   = pix & (HWV - 1);

    // ---------------- phase 1: 22 dots over 256 h_fea channels, 2 pixels ----------------
    const float* hp = g_hfea + (size_t)n * CCH * HWV + hw;
    u64 accA[11], accB[11];
#pragma unroll
    for (int j = 0; j < 11; j++) { accA[j] = 0ULL; accB[j] = 0ULL; }

#pragma unroll 1
    for (int c0 = 0; c0 < CCH; c0 += 8) {
        float2 hv[8];
#pragma unroll
        for (int u = 0; u < 8; u++) hv[u] = *(const float2*)(hp + (size_t)(c0 + u) * HWV);
#pragma unroll
        for (int u = 0; u < 8; u++) {
            u64 hA = dup2(hv[u].x);
            u64 hB = dup2(hv[u].y);
            const u64* wr = s_big + (size_t)(c0 + u) * 12;
#pragma unroll
            for (int jp = 0; jp < 11; jp++) {
                u64 w = wr[jp];
                accA[jp] = ffma2(hA, w, accA[jp]);
                accB[jp] = ffma2(hB, w, accB[jp]);
            }
        }
    }
    // transpose: hacc[j] = (dot_j(pixA), dot_j(pixB)); j<20 -> t pre, 20 -> decU, 21 -> decL
    u64 hacc[22];
#pragma unroll
    for (int jp = 0; jp < 11; jp++) {
        float ax, ay, bx, by;
        unpack2(accA[jp], ax, ay);
        unpack2(accB[jp], bx, by);
        hacc[2 * jp]     = pack2(ax, bx);
        hacc[2 * jp + 1] = pack2(ay, by);
    }

    // ---------------- phase 2: HID=10 graph ops, packed over the pixel pair ----------------
    const size_t vb = (size_t)n * HIDN * HWV + hw;
    u64 xu[10], xl[10];
#pragma unroll
    for (int i = 0; i < 10; i++) {
        xu[i] = *(const u64*)(g_xhu + vb + (size_t)i * HWV);
        xl[i] = *(const u64*)(g_xhl + vb + (size_t)i * HWV);
    }

    u64 dpu[10], dpl[10], agu, agl;
    {
        u64 tt[20];
#pragma unroll
        for (int o = 0; o < 20; o++) {
            u64 a = hacc[o];
#pragma unroll
            for (int k = 0; k < 10; k++) a = ffma2(xu[k], s_small[o * 20 + k], a);
#pragma unroll
            for (int k = 0; k < 10; k++) a = ffma2(xl[k], s_small[o * 20 + 10 + k], a);
            tt[o] = relu2(a);
        }
#pragma unroll
        for (int o = 0; o < 10; o++) {
            u64 a = 0ULL, b = 0ULL;
#pragma unroll
            for (int i = 0; i < 10; i++) {
                a = ffma2(tt[i],      s_small[400 + o * 10 + i], a);
                b = ffma2(tt[10 + i], s_small[500 + o * 10 + i], b);
            }
            dpu[o] = relu2(a);
            dpl[o] = relu2(b);
        }
    }
    {
        u64 a = s_small[620], b = s_small[621];
#pragma unroll
        for (int i = 0; i < 10; i++) {
            a = ffma2(xu[i], s_small[600 + i], a);
            b = ffma2(xl[i], s_small[610 + i], b);
        }
        agu = sigmoid2(a);
        agl = sigmoid2(b);
    }
    u64 xfv[10];
#pragma unroll
    for (int i = 0; i < 10; i++) xfv[i] = *(const u64*)(g_xf + vb + (size_t)i * HWV);

    // ================= U half =================
    {
        u64 msg[10];
#pragma unroll
        for (int i = 0; i < 10; i++) msg[i] = 0ULL;
#pragma unroll
        for (int pp = 0; pp < 4; pp++) {
            u64 xv[10];
            const float* xpp = g_xp + ((size_t)(pp * NIMG + n) * HIDN) * HWV + hw;
#pragma unroll
            for (int i = 0; i < 10; i++) xv[i] = *(const u64*)(xpp + (size_t)i * HWV);
            u64 s = s_small[662 + pp];
#pragma unroll
            for (int i = 0; i < 10; i++) s = ffma2(xv[i], s_small[622 + pp * 10 + i], s);
            u64 ca = sigmoid2(s);
#pragma unroll
            for (int i = 0; i < 10; i++) msg[i] = ffma2(xv[i], ca, msg[i]);
        }
        u64 m[10];
#pragma unroll
        for (int o = 0; o < 10; o++) {
            u64 a = 0ULL;
#pragma unroll
            for (int i = 0; i < 10; i++) a = ffma2(xu[i],  s_small[666 + o * 20 + i], a);
#pragma unroll
            for (int i = 0; i < 10; i++) a = ffma2(msg[i], s_small[666 + o * 20 + 10 + i], a);
            m[o] = relu2(a);                  // xphu
            m[o] = ffma2(dpl[o], agl, m[o]);  // + xlh = dp_l*ag_l + xh_u*ag_u
            m[o] = ffma2(xu[o],  agu, m[o]);
        }
        // decU
        u64 attu;
        {
            u64 s = fadd2(hacc[20], s_small[1108]);
#pragma unroll
            for (int i = 0; i < 10; i++) s = ffma2(xfv[i], s_small[1088 + i], s);
#pragma unroll
            for (int i = 0; i < 10; i++) s = ffma2(xu[i],  s_small[1098 + i], s);
            attu = sigmoid2(s);
        }
        *(u64*)(out + OUT_ATTU + (size_t)n * HWV + hw) = attu;
        {
            u64 xfa[10];
#pragma unroll
            for (int i = 0; i < 10; i++) xfa[i] = fmul2(xfv[i], attu);
#pragma unroll
            for (int o = 0; o < 10; o++) {
                u64 a = 0ULL;
#pragma unroll
                for (int i = 0; i < 10; i++) a = ffma2(xfa[i], s_small[1109 + o * 10 + i], a);
                m[o] = fadd2(m[o], relu2(a)); // + xfhu
            }
        }
        // update U
#pragma unroll
        for (int o = 0; o < 10; o++) {
            u64 g  = s_small[1530 + o];
            u64 cd = 0ULL;
#pragma unroll
            for (int i = 0; i < 10; i++) {
                g  = ffma2(xu[i], s_small[1330 + o * 20 + i], g);
                cd = ffma2(xu[i], s_small[1540 + o * 20 + i], cd);
            }
#pragma unroll
            for (int i = 0; i < 10; i++) {
                g  = ffma2(m[i], s_small[1330 + o * 20 + 10 + i], g);
                cd = ffma2(m[i], s_small[1540 + o * 20 + 10 + i], cd);
            }
            g  = sigmoid2(g);
            cd = relu2(cd);
            u64 res = ffma2(g, fadd2(cd, neg2(xu[o])), xu[o]);  // xu*(1-g)+cd*g
            *(u64*)(out + (size_t)(n * HIDN + o) * HWV + hw) = res;
        }
    }

    // ================= L half =================
    {
        u64 msg[10];
#pragma unroll
        for (int i = 0; i < 10; i++) msg[i] = 0ULL;
#pragma unroll
        for (int pp = 0; pp < 2; pp++) {
            u64 xv[10];
            const float* xpp = g_xp + ((size_t)((4 + pp) * NIMG + n) * HIDN) * HWV + hw;
#pragma unroll
            for (int i = 0; i < 10; i++) xv[i] = *(const u64*)(xpp + (size_t)i * HWV);
            u64 s = s_small[886 + pp];
#pragma unroll
            for (int i = 0; i < 10; i++) s = ffma2(xv[i], s_small[866 + pp * 10 + i], s);
            u64 ca = sigmoid2(s);
#pragma unroll
            for (int i = 0; i < 10; i++) msg[i] = ffma2(xv[i], ca, msg[i]);
        }
        u64 m[10];
#pragma unroll
        for (int o = 0; o < 10; o++) {
            u64 a = 0ULL;
#pragma unroll
            for (int i = 0; i < 10; i++) a = ffma2(xl[i],  s_small[888 + o * 20 + i], a);
#pragma unroll
            for (int i = 0; i < 10; i++) a = ffma2(msg[i], s_small[888 + o * 20 + 10 + i], a);
            m[o] = relu2(a);                  // xphl
            m[o] = ffma2(dpu[o], agu, m[o]);  // + xuh = dp_u*ag_u + xh_l*ag_l
            m[o] = ffma2(xl[o],  agl, m[o]);
        }
        // decL
        u64 attl;
        {
            u64 s = fadd2(hacc[21], s_small[1229]);
#pragma unroll
            for (int i = 0; i < 10; i++) s = ffma2(xfv[i], s_small[1209 + i], s);
#pragma unroll
            for (int i = 0; i < 10; i++) s = ffma2(xl[i],  s_small[1219 + i], s);
            attl = sigmoid2(s);
        }
        *(u64*)(out + OUT_ATTL + (size_t)n * HWV + hw) = attl;
        {
            u64 xfa[10];
#pragma unroll
            for (int i = 0; i < 10; i++) xfa[i] = fmul2(xfv[i], attl);
#pragma unroll
            for (int o = 0; o < 10; o++) {
                u64 a = 0ULL;
#pragma unroll
                for (int i = 0; i < 10; i++) a = ffma2(xfa[i], s_small[1230 + o * 10 + i], a);
                m[o] = fadd2(m[o], relu2(a)); // + xfhl
            }
        }
        // update L
#pragma unroll
        for (int o = 0; o < 10; o++) {
            u64 g  = s_small[1940 + o];
            u64 cd = 0ULL;
#pragma unroll
            for (int i = 0; i < 10; i++) {
                g  = ffma2(xl[i], s_small[1740 + o * 20 + i], g);
                cd = ffma2(xl[i], s_small[1950 + o * 20 + i], cd);
            }
#pragma unroll
            for (int i = 0; i < 10; i++) {
                g  = ffma2(m[i], s_small[1740 + o * 20 + 10 + i], g);
                cd = ffma2(m[i], s_small[1950 + o * 20 + 10 + i], cd);
            }
            g  = sigmoid2(g);
            cd = relu2(cd);
            u64 res = ffma2(g, fadd2(cd, neg2(xl[o])), xl[o]);
            *(u64*)(out + OUT_XHL + (size_t)(n * HIDN + o) * HWV + hw) = res;
        }
    }
}

extern "C" void kernel_launch(void* const* d_in, const int* in_sizes, int n_in,
                              void* d_out, int out_size) {
    P27 p;
    for (int i = 0; i < 27; i++) p.a[i] = (const float*)d_in[i];
    p.out = (float*)d_out;
    hg_kernel<<<296, 256>>>(p);
}